// round 16
// baseline (speedup 1.0000x reference)
#include <cuda_runtime.h>
#include <cuda_fp16.h>
#include <cstdint>

#define BB   128
#define TT   1024
#define HH   512
#define VV   256
#define NCTA 128      // total CTAs = 2 groups x 64
#define NCG  64       // CTAs per group
#define NTHR 256

// ---------------------------------------------------------------------------
// Device scratch (allocation-free).
// Chunk format (per 64x128 fp16 tile = 8192 halves = 16 KB): row*256B rows,
// 16B-unit u stored at (u ^ (row & 15)) — identical to SMEM slot layout.
// g_h1c double-buffered by t&1 (e1 is hoisted above wait(bH)).
// ---------------------------------------------------------------------------
__device__ __half g_h1c[2 * 2 * 4 * 8192];           // [buf][g][kc][8192]
__device__ __half g_h2all16[(size_t)TT * 65536];     // [t][g][kc][8192]
__device__ __half g_Wlin16[VV * HH];                 // [v][k], row-XOR swz
__device__ float  g_xT[TT * BB];                     // x transposed [t][b]
__device__ unsigned g_barcnt, g_bargen;              // global init barrier
// two-level split-phase barriers: 4 barriers x 4 sub-counters, 256B padding
__device__ unsigned g_sub[4 * 4 * 64];               // [bar][sub] * 64-word pad
__device__ unsigned g_mst[4 * 64];                   // [bar] * 64-word pad
__device__ unsigned g_genw[4 * 64];                  // [bar] * 64-word pad

// ---------------------------------------------------------------------------
// Persistent SMEM: 5 slots x 16KB + 3 W x 32KB + G 8KB + misc
// ---------------------------------------------------------------------------
#define SLOT(c)   ((c) * 16384)
#define W1O       81920
#define W2HO      (W1O + 32768)
#define W2IO      (W1O + 65536)
#define GOFF      (W1O + 98304)
#define MISC      (GOFF + 8192)
#define SMEM_TOTAL (MISC + 512)

// lin kernel SMEM
#define LA0 0
#define LA1 32768
#define LB0 65536
#define LB1 131072
#define LBL 196608
#define LIN_SMEM (LBL + 1024)

__device__ __forceinline__ uint32_t smem_u32(const void* p) {
    uint32_t a;
    asm("{ .reg .u64 t; cvta.to.shared.u64 t, %1; cvt.u32.u64 %0, t; }"
        : "=r"(a) : "l"(p));
    return a;
}
__device__ __forceinline__ float sigf(float x) {
    return __fdividef(1.0f, 1.0f + __expf(-x));
}
__device__ __forceinline__ float tanhf_fast(float x) {
    return 1.0f - __fdividef(2.0f, __expf(2.0f * x) + 1.0f);
}

// ---------------------------------------------------------------------------
// Global init barrier (128 CTAs)
// ---------------------------------------------------------------------------
__device__ __forceinline__ void grid_barrier() {
    __threadfence();
    __syncthreads();
    if (threadIdx.x == 0) {
        unsigned gen = *(volatile unsigned*)&g_bargen;
        unsigned arrived = atomicAdd(&g_barcnt, 1u);
        if (arrived == NCTA - 1) {
            *(volatile unsigned*)&g_barcnt = 0u;
            __threadfence();
            atomicAdd(&g_bargen, 1u);
        } else {
            while (*(volatile unsigned*)&g_bargen == gen) { }
        }
    }
    __syncthreads();
    __threadfence();
}

// ---------------------------------------------------------------------------
// Two-level split-phase barrier (per group: 64 arrivers = 4 subs x 16).
// arrive: data fence -> sub atomic; 16th of a sub bumps master; 4th master
// publishes gen. wait: poll gen, then acquire fence.
// Rounds are monotonic; cross-round overlap impossible (proven by the
// bW->bH->bW dependency chain).
// ---------------------------------------------------------------------------
__device__ __forceinline__ void bar_arrive(int idx, int sub, unsigned round) {
    __threadfence();
    __syncthreads();
    if (threadIdx.x == 0) {
        unsigned a = atomicAdd(&g_sub[(idx * 4 + sub) * 64], 1u);
        if (a == round * 16u + 15u) {
            __threadfence();
            unsigned m = atomicAdd(&g_mst[idx * 64], 1u);
            if (m == round * 4u + 3u) {
                __threadfence();
                atomicExch(&g_genw[idx * 64], round + 1u);
            }
        }
    }
}
__device__ __forceinline__ void bar_wait(int idx, unsigned round) {
    if (threadIdx.x == 0) {
        while (*(volatile unsigned*)&g_genw[idx * 64] < round + 1u) { }
    }
    __syncthreads();
    __threadfence();
}

// ---------------------------------------------------------------------------
// Primitives
// ---------------------------------------------------------------------------
__device__ __forceinline__ void cpa16(uint32_t dst, const void* src) {
    asm volatile("cp.async.cg.shared.global [%0], [%1], 16;" :: "r"(dst), "l"(src));
}
__device__ __forceinline__ void ldm4(uint32_t a[4], uint32_t addr) {
    asm volatile("ldmatrix.sync.aligned.m8n8.x4.shared.b16 {%0,%1,%2,%3}, [%4];"
                 : "=r"(a[0]), "=r"(a[1]), "=r"(a[2]), "=r"(a[3]) : "r"(addr));
}
__device__ __forceinline__ void mma16816(float d[4], const uint32_t a[4],
                                         const uint32_t b0, const uint32_t b1) {
    asm volatile(
        "mma.sync.aligned.m16n8k16.row.col.f32.f16.f16.f32 "
        "{%0,%1,%2,%3}, {%4,%5,%6,%7}, {%8,%9}, {%0,%1,%2,%3};"
        : "+f"(d[0]), "+f"(d[1]), "+f"(d[2]), "+f"(d[3])
        : "r"(a[0]), "r"(a[1]), "r"(a[2]), "r"(a[3]), "r"(b0), "r"(b1));
}

// Linear 16KB chunk stage: slot-formatted global chunk -> slot
__device__ __forceinline__ void issue_lin(uint32_t sb, int slot,
                                          const __half* __restrict__ src, int tid) {
    uint32_t base = sb + SLOT(slot);
#pragma unroll
    for (int i = 0; i < 4; ++i) {
        uint32_t off = (uint32_t)(i * NTHR + tid) * 16u;
        cpa16(base + off, (const char*)src + off);
    }
    asm volatile("cp.async.commit_group;");
}

// M=64 x N=32 tile; warp (mw = wid&3, nw = wid>>2)
__device__ __forceinline__ void compute_chunk(uint32_t sb, int slot, int kc,
                                              uint32_t wOff, float acc[2][4],
                                              int mw, int nw, int lane) {
    uint32_t arow = sb + SLOT(slot) + (mw * 16 + (lane & 15)) * 256;
    int Ra = lane & 15;
    int nn = nw * 16 + (lane & 7) + ((lane >> 4) << 3);
    int n7 = lane & 7;
#pragma unroll
    for (int kk = 0; kk < 8; ++kk) {
        uint32_t a[4];
        int ua = kk * 2 + (lane >> 4);
        ldm4(a, arow + ((uint32_t)(ua ^ Ra) << 4));
        uint32_t b[4];
        int ug = (kc * 8 + kk) * 2 + ((lane >> 3) & 1);
        ldm4(b, sb + wOff + (uint32_t)(nn * 1024 + ((ug ^ n7) << 4)));
        mma16816(acc[0], a, b[0], b[1]);
        mma16816(acc[1], a, b[2], b[3]);
    }
}
__device__ __forceinline__ void compute_chunk_dual(uint32_t sb, int slot, int kc,
                                                   uint32_t wA, float accA[2][4],
                                                   uint32_t wB, float accB[2][4],
                                                   int mw, int nw, int lane) {
    uint32_t arow = sb + SLOT(slot) + (mw * 16 + (lane & 15)) * 256;
    int Ra = lane & 15;
    int nn = nw * 16 + (lane & 7) + ((lane >> 4) << 3);
    int n7 = lane & 7;
#pragma unroll
    for (int kk = 0; kk < 8; ++kk) {
        uint32_t a[4];
        int ua = kk * 2 + (lane >> 4);
        ldm4(a, arow + ((uint32_t)(ua ^ Ra) << 4));
        int ug = (kc * 8 + kk) * 2 + ((lane >> 3) & 1);
        uint32_t boff = (uint32_t)(nn * 1024 + ((ug ^ n7) << 4));
        uint32_t b[4], b2[4];
        ldm4(b,  sb + wA + boff);
        ldm4(b2, sb + wB + boff);
        mma16816(accA[0], a, b[0], b[1]);
        mma16816(accA[1], a, b[2], b[3]);
        mma16816(accB[0], a, b2[0], b2[1]);
        mma16816(accB[1], a, b2[2], b2[3]);
    }
}
// G[col][row]: 32 cols x 64 rows f32
__device__ __forceinline__ void frag_to_smem(float* G, const float acc[2][4],
                                             int mw, int nw, int lane) {
    int r = mw * 16 + (lane >> 2);
#pragma unroll
    for (int nt = 0; nt < 2; ++nt) {
        int col = nw * 16 + nt * 8 + 2 * (lane & 3);
        G[col * 64 + r]           = acc[nt][0];
        G[(col + 1) * 64 + r]     = acc[nt][1];
        G[col * 64 + r + 8]       = acc[nt][2];
        G[(col + 1) * 64 + r + 8] = acc[nt][3];
    }
}

// ---------------------------------------------------------------------------
// Persistent HMMA LSTM, 2 independent batch groups.
// Group g = cta>>6 (batch rows [64g,64g+64)); cl = cta&63 owns hidden units
// [8cl, 8cl+8) for both layers (N=32 gate cols, col = gate*8 + u).
// ---------------------------------------------------------------------------
__global__ void __launch_bounds__(NTHR, 1)
lstm_persist(const float* __restrict__ x,
             const float* __restrict__ Wih1, const float* __restrict__ Whh1,
             const float* __restrict__ bih1, const float* __restrict__ bhh1,
             const float* __restrict__ Wih2, const float* __restrict__ Whh2,
             const float* __restrict__ bih2, const float* __restrict__ bhh2,
             const float* __restrict__ Wlin) {
    extern __shared__ char smem[];
    const uint32_t sb = smem_u32(smem);
    const int cta = blockIdx.x;
    const int grp = cta >> 6;
    const int cl  = cta & 63;
    const int sub = cl & 3;
    const int tid = threadIdx.x;
    const int wid = tid >> 5;
    const int lane = tid & 31;
    const int mw = wid & 3, nw = wid >> 2;

    float* G     = (float*)(smem + GOFF);
    float* bias1 = (float*)(smem + MISC);
    float* wih1  = (float*)(smem + MISC + 128);
    float* bias2 = (float*)(smem + MISC + 256);

    // ---- Prologue: recurrent weights -> SMEM fp16 [n=32][k=512], XOR swz ----
    for (int m = 0; m < 3; ++m) {
        const float* W = (m == 0) ? Whh1 : (m == 1) ? Whh2 : Wih2;
        uint32_t wO = W1O + m * 32768u;
        for (int q = tid; q < 16384; q += NTHR) {
            int n = q >> 9, k = q & 511;
            int R = (n >> 3) * HH + cl * 8 + (n & 7);
            uint32_t off = (uint32_t)(n * 1024 + (((k >> 3) ^ (n & 7)) << 4) +
                                      (k & 7) * 2);
            *(__half*)(smem + wO + off) = __float2half(W[R * HH + k]);
        }
    }
    if (tid < 32) {
        int n = tid;
        int R = (n >> 3) * HH + cl * 8 + (n & 7);
        bias1[n] = bih1[R] + bhh1[R];
        wih1[n]  = Wih1[R];
        bias2[n] = bih2[R] + bhh2[R];
    }

    // ---- Global init: x transpose, W_lin fp16 swizzled ----
    const int gtid = cta * NTHR + tid;
    const int gstr = NCTA * NTHR;
    for (int i = gtid; i < TT * BB; i += gstr) {
        int t = i >> 7, b = i & (BB - 1);
        g_xT[i] = x[b * TT + t];
    }
    for (int i = gtid; i < VV * HH; i += gstr) {
        int v = i >> 9, k = i & 511;
        g_Wlin16[v * HH + (((k >> 3) ^ (v & 7)) << 3) + (k & 7)] =
            __float2half(Wlin[v * HH + k]);
    }
    // zero slots 0..3 (t=0 reads zeros for h2(-1))
    for (int i = tid; i < 16384; i += NTHR) ((uint32_t*)smem)[i] = 0u;
    __syncthreads();
    grid_barrier();
    if (cta == 0 && tid == 0) {
        for (int i = 0; i < 16; ++i) g_sub[i * 64] = 0u;
        for (int i = 0; i < 4; ++i) { g_mst[i * 64] = 0u; g_genw[i * 64] = 0u; }
    }
    grid_barrier();

    // ---- Time loop ----
    const int bW = grp * 2 + 0;    // h1 barrier
    const int bH = grp * 2 + 1;    // h2 barrier
    float c1st[2] = {0, 0}, c2st[2] = {0, 0};
    float acc1[2][4] = {{0, 0, 0, 0}, {0, 0, 0, 0}};
    const int erow = tid & 63, eup = tid >> 6;
    const uint32_t eoff =
        (uint32_t)((cl >> 4) * 8192 + erow * 128 +
                   ((((cl & 15) ^ (erow & 15)) << 3) + 2 * eup));  // halves

    for (unsigned t = 0; t < TT; ++t) {
        const uint32_t h1base = (t & 1u) * 65536u + grp * 32768u;
        const __half* h1src = g_h1c + h1base;

        // ---- e1(t) FIRST (local-only inputs): gates1 -> h1(t) buf[t&1] ----
        frag_to_smem(G, acc1, mw, nw, lane);
        __syncthreads();
        {
            float xv = g_xT[t * BB + grp * 64 + erow];
            union { uint32_t u; __half h[2]; } ph;
#pragma unroll
            for (int q = 0; q < 2; ++q) {
                int u = 2 * eup + q;
                float gi = G[u * 64 + erow]        + bias1[u]      + xv * wih1[u];
                float gf = G[(8 + u) * 64 + erow]  + bias1[8 + u]  + xv * wih1[8 + u];
                float gg = G[(16 + u) * 64 + erow] + bias1[16 + u] + xv * wih1[16 + u];
                float go = G[(24 + u) * 64 + erow] + bias1[24 + u] + xv * wih1[24 + u];
                float cn = sigf(gf) * c1st[q] + sigf(gi) * tanhf_fast(gg);
                c1st[q] = cn;
                ph.h[q] = __float2half(sigf(go) * tanhf_fast(cn));
            }
            *(uint32_t*)&g_h1c[h1base + eoff] = ph.u;
        }
        bar_arrive(bW, sub, t);    // h1(t) posted; ages through H2 phase

        // ---- now wait for h2(t-1) (release latency hidden behind e1) ----
        if (t > 0) {
            bar_wait(bH, t - 1);
            const __half* h2src = g_h2all16 + (size_t)(t - 1) * 65536 + grp * 32768;
            issue_lin(sb, 0, h2src,         tid);
            issue_lin(sb, 1, h2src + 8192,  tid);
            issue_lin(sb, 2, h2src + 16384, tid);
            issue_lin(sb, 3, h2src + 24576, tid);
        }

        float acc2[2][4] = {{0, 0, 0, 0}, {0, 0, 0, 0}};
#pragma unroll
        for (int q = 0; q < 2; ++q)
#pragma unroll
            for (int j = 0; j < 4; ++j) acc1[q][j] = 0.0f;

        // ---- H2 phase with interleaved h1 prefetch (5-slot schedule) ----
        asm volatile("cp.async.wait_group 3;");
        __syncthreads();
        compute_chunk(sb, 0, 0, W2HO, acc2, mw, nw, lane);

        asm volatile("cp.async.wait_group 2;");
        __syncthreads();
        compute_chunk(sb, 1, 1, W2HO, acc2, mw, nw, lane);

        bar_wait(bW, t);                      // aged: e1 + 2 chunks
        issue_lin(sb, 4, h1src,         tid);

        asm volatile("cp.async.wait_group 2;");
        __syncthreads();
        compute_chunk(sb, 2, 2, W2HO, acc2, mw, nw, lane);
        issue_lin(sb, 0, h1src + 8192,  tid);

        asm volatile("cp.async.wait_group 2;");
        __syncthreads();
        compute_chunk(sb, 3, 3, W2HO, acc2, mw, nw, lane);
        issue_lin(sb, 1, h1src + 16384, tid);

        // ---- H1 phase: dual GEMM (acc2 += W2i.h1 ; acc1 = W1.h1) ----
        asm volatile("cp.async.wait_group 2;");
        __syncthreads();
        compute_chunk_dual(sb, 4, 0, W2IO, acc2, W1O, acc1, mw, nw, lane);
        issue_lin(sb, 2, h1src + 24576, tid);

        asm volatile("cp.async.wait_group 2;");
        __syncthreads();
        compute_chunk_dual(sb, 0, 1, W2IO, acc2, W1O, acc1, mw, nw, lane);

        asm volatile("cp.async.wait_group 1;");
        __syncthreads();
        compute_chunk_dual(sb, 1, 2, W2IO, acc2, W1O, acc1, mw, nw, lane);

        asm volatile("cp.async.wait_group 0;");
        __syncthreads();
        compute_chunk_dual(sb, 2, 3, W2IO, acc2, W1O, acc1, mw, nw, lane);

        // ---- e2(t): gates2 -> h2(t) chunk-format ----
        frag_to_smem(G, acc2, mw, nw, lane);
        __syncthreads();
        {
            union { uint32_t u; __half h[2]; } ph;
#pragma unroll
            for (int q = 0; q < 2; ++q) {
                int u = 2 * eup + q;
                float gi = G[u * 64 + erow]        + bias2[u];
                float gf = G[(8 + u) * 64 + erow]  + bias2[8 + u];
                float gg = G[(16 + u) * 64 + erow] + bias2[16 + u];
                float go = G[(24 + u) * 64 + erow] + bias2[24 + u];
                float cn = sigf(gf) * c2st[q] + sigf(gi) * tanhf_fast(gg);
                c2st[q] = cn;
                ph.h[q] = __float2half(sigf(go) * tanhf_fast(cn));
            }
            *(uint32_t*)&g_h2all16[(size_t)t * 65536 + grp * 32768 + eoff] = ph.u;
        }
        bar_arrive(bH, sub, t);
    }
}

// ---------------------------------------------------------------------------
// Final phase (HMMA): per t: logits[128,256] = h2(t) @ Wlin^T + b, softmax.
// ---------------------------------------------------------------------------
__global__ void __launch_bounds__(NTHR)
lin_hmma(const float* __restrict__ blin, float* __restrict__ out) {
    extern __shared__ char smem[];
    const uint32_t sb = smem_u32(smem);
    const int t   = blockIdx.x;
    const int tid = threadIdx.x;
    const int wid = tid >> 5;
    const int lane = tid & 31;
    float* bl_s = (float*)(smem + LBL);
    if (tid < VV) bl_s[tid] = blin[tid];

    const char* Asrc = (const char*)g_h2all16 + (size_t)t * 131072;

    auto issue = [&](int kc, int ib) {
        uint32_t ab = sb + (ib ? LA1 : LA0);
#pragma unroll
        for (int i = 0; i < 8; ++i) {
            uint32_t off = (uint32_t)(i * NTHR + tid) * 16u;
            uint32_t g = off >> 14, loff = off & 16383u;
            cpa16(ab + off, Asrc + g * 65536 + (uint32_t)kc * 16384 + loff);
        }
        uint32_t bb = sb + (ib ? LB1 : LB0);
#pragma unroll
        for (int i = 0; i < 16; ++i) {
            int idx = i * NTHR + tid;
            int n = idx >> 4, u = idx & 15;
            cpa16(bb + (uint32_t)(n * 256 + u * 16),
                  (const char*)g_Wlin16 + n * 1024 + kc * 256 + u * 16);
        }
        asm volatile("cp.async.commit_group;");
    };

    float acc[32][4];
#pragma unroll
    for (int nt = 0; nt < 32; ++nt)
#pragma unroll
        for (int j = 0; j < 4; ++j) acc[nt][j] = 0.0f;

    issue(0, 0);
    issue(1, 1);
    const int Ra = lane & 15;
    const int n7 = lane & 7;
    const int nbase = (lane & 7) + ((lane >> 4) << 3);
    const int ugb = (lane >> 3) & 1;

    for (int kc = 0; kc < 4; ++kc) {
        if (kc < 3) asm volatile("cp.async.wait_group 1;");
        else        asm volatile("cp.async.wait_group 0;");
        __syncthreads();
        uint32_t ab = sb + ((kc & 1) ? LA1 : LA0);
        uint32_t bb = sb + ((kc & 1) ? LB1 : LB0);
        uint32_t arow = ab + (wid * 16 + (lane & 15)) * 256;
#pragma unroll
        for (int kk = 0; kk < 8; ++kk) {
            uint32_t a[4];
            int ua = kk * 2 + (lane >> 4);
            ldm4(a, arow + ((uint32_t)(ua ^ Ra) << 4));
            int ug = kk * 2 + ugb;
            uint32_t bsw = (uint32_t)((ug ^ n7) << 4);
#pragma unroll
            for (int ntp = 0; ntp < 16; ++ntp) {
                uint32_t b[4];
                ldm4(b, bb + (uint32_t)((nbase + ntp * 16) * 256) + bsw);
                mma16816(acc[2 * ntp],     a, b[0], b[1]);
                mma16816(acc[2 * ntp + 1], a, b[2], b[3]);
            }
        }
        __syncthreads();
        if (kc < 2) issue(kc + 2, kc & 1);
    }

    // ---- bias + softmax (rows r0 and r0+8) ----
    const int r0 = wid * 16 + (lane >> 2);
    const int cb = 2 * (lane & 3);
    float m0 = -1e30f, m1 = -1e30f;
#pragma unroll
    for (int nt = 0; nt < 32; ++nt) {
        float b0 = bl_s[nt * 8 + cb], b1 = bl_s[nt * 8 + cb + 1];
        acc[nt][0] += b0; acc[nt][1] += b1;
        acc[nt][2] += b0; acc[nt][3] += b1;
        m0 = fmaxf(m0, fmaxf(acc[nt][0], acc[nt][1]));
        m1 = fmaxf(m1, fmaxf(acc[nt][2], acc[nt][3]));
    }
    m0 = fmaxf(m0, __shfl_xor_sync(0xffffffffu, m0, 1));
    m0 = fmaxf(m0, __shfl_xor_sync(0xffffffffu, m0, 2));
    m1 = fmaxf(m1, __shfl_xor_sync(0xffffffffu, m1, 1));
    m1 = fmaxf(m1, __shfl_xor_sync(0xffffffffu, m1, 2));
    float s0 = 0.0f, s1 = 0.0f;
#pragma unroll
    for (int nt = 0; nt < 32; ++nt) {
        acc[nt][0] = __expf(acc[nt][0] - m0); s0 += acc[nt][0];
        acc[nt][1] = __expf(acc[nt][1] - m0); s0 += acc[nt][1];
        acc[nt][2] = __expf(acc[nt][2] - m1); s1 += acc[nt][2];
        acc[nt][3] = __expf(acc[nt][3] - m1); s1 += acc[nt][3];
    }
    s0 += __shfl_xor_sync(0xffffffffu, s0, 1);
    s0 += __shfl_xor_sync(0xffffffffu, s0, 2);
    s1 += __shfl_xor_sync(0xffffffffu, s1, 1);
    s1 += __shfl_xor_sync(0xffffffffu, s1, 2);
    float inv0 = __fdividef(1.0f, s0);
    float inv1 = __fdividef(1.0f, s1);
    float* o0 = out + ((size_t)r0 * TT + t) * VV;
    float* o1 = out + ((size_t)(r0 + 8) * TT + t) * VV;
#pragma unroll
    for (int nt = 0; nt < 32; ++nt) {
        int c = nt * 8 + cb;
        *(float2*)(o0 + c) = make_float2(acc[nt][0] * inv0, acc[nt][1] * inv0);
        *(float2*)(o1 + c) = make_float2(acc[nt][2] * inv1, acc[nt][3] * inv1);
    }
}

// ---------------------------------------------------------------------------
extern "C" void kernel_launch(void* const* d_in, const int* in_sizes, int n_in,
                              void* d_out, int out_size) {
    const float* x    = (const float*)d_in[0];
    const float* Wih1 = (const float*)d_in[1];
    const float* Whh1 = (const float*)d_in[2];
    const float* bih1 = (const float*)d_in[3];
    const float* bhh1 = (const float*)d_in[4];
    const float* Wih2 = (const float*)d_in[5];
    const float* Whh2 = (const float*)d_in[6];
    const float* bih2 = (const float*)d_in[7];
    const float* bhh2 = (const float*)d_in[8];
    const float* Wlin = (const float*)d_in[9];
    const float* blin = (const float*)d_in[10];

    cudaFuncSetAttribute(lstm_persist, cudaFuncAttributeMaxDynamicSharedMemorySize,
                         SMEM_TOTAL);
    cudaFuncSetAttribute(lin_hmma, cudaFuncAttributeMaxDynamicSharedMemorySize,
                         LIN_SMEM);

    lstm_persist<<<NCTA, NTHR, SMEM_TOTAL>>>(x, Wih1, Whh1, bih1, bhh1,
                                             Wih2, Whh2, bih2, bhh2, Wlin);
    lin_hmma<<<TT, NTHR, LIN_SMEM>>>(blin, (float*)d_out);
}